// round 1
// baseline (speedup 1.0000x reference)
#include <cuda_runtime.h>
#include <cstdint>

#define B_ 16
#define N_ 577
#define H_ 12
#define D_ 64
#define C_ 768
#define BH_ 192
#define M_ 9232
#define KTS 580
#define SCALE_ 0.125f

// ---------------- device scratch (no cudaMalloc allowed) ----------------
__device__ float g_q[BH_ * N_ * D_];          // (bh, n, d)
__device__ float g_kT[BH_ * D_ * KTS];        // (bh, d, n) padded rows
__device__ float g_v[BH_ * N_ * D_];          // (bh, n, d)
__device__ float g_ao[M_ * C_];               // attention out, (b*n, c)
__device__ unsigned char g_xdis[N_ * N_];
__device__ unsigned char g_ydis[N_ * N_];

// ---------------- relative-distance index tables ----------------
__global__ void init_dis_kernel() {
  int idx = blockIdx.x * blockDim.x + threadIdx.x;
  if (idx >= N_ * N_) return;
  int n = idx / N_, m = idx % N_;
  unsigned char xd = 0, yd = 0;
  if (n > 0 && m > 0) {
    int pn = n - 1, pm = m - 1;
    int dx = (pm % 24) - (pn % 24);
    int dy = (pm / 24) - (pn / 24);
    dx = max(-24, min(24, dx));
    dy = max(-24, min(24, dy));
    xd = (unsigned char)(dx + 25);
    yd = (unsigned char)(dy + 25);
  }
  g_xdis[idx] = xd;
  g_ydis[idx] = yd;
}

// ---------------- SGEMM: C[m,c] = sum_k A[m,k] * W[c,k] ----------------
#define BM 128
#define BN 128
#define BK 16

// MODE 0: store into g_q / g_kT / g_v (QKV projection)
// MODE 1: plain row-major store into `out` (final projection), A read from g_ao
template <int MODE>
__global__ __launch_bounds__(256)
void sgemm_kernel(const float* __restrict__ Ain, const float* __restrict__ W,
                  float* __restrict__ out) {
  __shared__ float As[BK][BM + 4];
  __shared__ float Bs[BK][BN + 4];
  const float* A = (MODE == 0) ? Ain : (const float*)g_ao;
  const int row0 = blockIdx.y * BM;
  const int col0 = blockIdx.x * BN;
  const int tid = threadIdx.x;
  const int tr = tid >> 4, tc = tid & 15;
  const int lr = tid >> 1, lk = (tid & 1) << 3;

  float acc[8][8];
#pragma unroll
  for (int i = 0; i < 8; i++)
#pragma unroll
    for (int j = 0; j < 8; j++) acc[i][j] = 0.f;

  for (int k0 = 0; k0 < C_; k0 += BK) {
    float4 a0, a1;
    int grow = row0 + lr;
    if (grow < M_) {
      const float* ap = A + (size_t)grow * C_ + k0 + lk;
      a0 = *(const float4*)ap;
      a1 = *(const float4*)(ap + 4);
    } else {
      a0 = make_float4(0.f, 0.f, 0.f, 0.f);
      a1 = a0;
    }
    const float* wp = W + (size_t)(col0 + lr) * C_ + k0 + lk;
    float4 b0 = *(const float4*)wp;
    float4 b1 = *(const float4*)(wp + 4);
    __syncthreads();
    As[lk + 0][lr] = a0.x; As[lk + 1][lr] = a0.y;
    As[lk + 2][lr] = a0.z; As[lk + 3][lr] = a0.w;
    As[lk + 4][lr] = a1.x; As[lk + 5][lr] = a1.y;
    As[lk + 6][lr] = a1.z; As[lk + 7][lr] = a1.w;
    Bs[lk + 0][lr] = b0.x; Bs[lk + 1][lr] = b0.y;
    Bs[lk + 2][lr] = b0.z; Bs[lk + 3][lr] = b0.w;
    Bs[lk + 4][lr] = b1.x; Bs[lk + 5][lr] = b1.y;
    Bs[lk + 6][lr] = b1.z; Bs[lk + 7][lr] = b1.w;
    __syncthreads();
#pragma unroll
    for (int k = 0; k < BK; k++) {
      float ar[8], br[8];
      *(float4*)&ar[0] = *(const float4*)&As[k][tr * 8];
      *(float4*)&ar[4] = *(const float4*)&As[k][tr * 8 + 4];
      *(float4*)&br[0] = *(const float4*)&Bs[k][tc * 8];
      *(float4*)&br[4] = *(const float4*)&Bs[k][tc * 8 + 4];
#pragma unroll
      for (int i = 0; i < 8; i++)
#pragma unroll
        for (int j = 0; j < 8; j++) acc[i][j] += ar[i] * br[j];
    }
  }

  const int c0 = col0 + tc * 8;
  if (MODE == 1) {
#pragma unroll
    for (int i = 0; i < 8; i++) {
      int m = row0 + tr * 8 + i;
      if (m >= M_) break;
      float* dst = out + (size_t)m * C_ + c0;
      *(float4*)dst = make_float4(acc[i][0], acc[i][1], acc[i][2], acc[i][3]);
      *(float4*)(dst + 4) = make_float4(acc[i][4], acc[i][5], acc[i][6], acc[i][7]);
    }
  } else {
    const int which = c0 / C_;         // 0=q 1=k 2=v
    const int rem = c0 % C_;
    const int h = rem / D_;
    const int d0 = rem % D_;
#pragma unroll
    for (int i = 0; i < 8; i++) {
      int m = row0 + tr * 8 + i;
      if (m >= M_) break;
      int b = m / N_, n = m % N_;
      int bh = b * H_ + h;
      if (which == 1) {
        size_t base = ((size_t)bh * D_ + d0) * KTS + n;
#pragma unroll
        for (int j = 0; j < 8; j++) g_kT[base + (size_t)j * KTS] = acc[i][j];
      } else {
        float* dst = (which == 0 ? g_q : g_v) + ((size_t)bh * N_ + n) * D_ + d0;
        *(float4*)dst = make_float4(acc[i][0], acc[i][1], acc[i][2], acc[i][3]);
        *(float4*)(dst + 4) = make_float4(acc[i][4], acc[i][5], acc[i][6], acc[i][7]);
      }
    }
  }
}

// ---------------- fused attention ----------------
#define ROWS 16
#define SPAD 584
#define ATH 128

struct __align__(16) AttnSmem {
  float qT[64][20];        // q transposed (d-major)
  float S[ROWS][SPAD];     // score / exp row buffer
  float kv[8704];          // K tile as [64][132] (d-major) OR V tile as [128][68]
  float embx[50 * 32];
  float emby[50 * 32];
  float bx[ROWS][52];      // px (q phase), then binx (v phase)
  float by[ROWS][52];      // py, then biny
  float red[ROWS][68];     // half-reduction buffer
  float rowsum[ROWS];
};

__global__ __launch_bounds__(ATH, 2)
void attn_kernel(const float* __restrict__ qxe, const float* __restrict__ qye,
                 const float* __restrict__ vxe, const float* __restrict__ vye) {
  extern __shared__ char smraw[];
  AttnSmem& sm = *reinterpret_cast<AttnSmem*>(smraw);
  const int bh = blockIdx.y;
  const int row0 = blockIdx.x * ROWS;
  const int tid = threadIdx.x;
  const int lane = tid & 31, wid = tid >> 5;

  // ---- load q (transposed) + q embeddings ----
  for (int f = tid; f < ROWS * 16; f += ATH) {
    int r = f >> 4, c4 = (f & 15) << 2;
    int n = row0 + r;
    float4 v = (n < N_) ? *(const float4*)(g_q + ((size_t)bh * N_ + n) * D_ + c4)
                        : make_float4(0.f, 0.f, 0.f, 0.f);
    sm.qT[c4 + 0][r] = v.x; sm.qT[c4 + 1][r] = v.y;
    sm.qT[c4 + 2][r] = v.z; sm.qT[c4 + 3][r] = v.w;
  }
  for (int f = tid; f < 400; f += ATH) ((float4*)sm.embx)[f] = ((const float4*)qxe)[f];
  for (int f = tid; f < 400; f += ATH) ((float4*)sm.emby)[f] = ((const float4*)qye)[f];
  __syncthreads();

  // ---- px/py: project q onto embedding tables (16 x 50 each) ----
  for (int idx = tid; idx < ROWS * 50; idx += ATH) {
    int r = idx / 50, t = idx % 50;
    float ax = 0.f, ay = 0.f;
#pragma unroll
    for (int d = 0; d < 32; d++) {
      ax += sm.qT[d][r] * sm.embx[t * 32 + d];
      ay += sm.qT[d + 32][r] * sm.emby[t * 32 + d];
    }
    sm.bx[r][t] = ax;
    sm.by[r][t] = ay;
  }
  __syncthreads();

  // ---- QK + relative bias ----
  const int qtr = wid;   // 4 row-groups of 4
  const int qtc = lane;  // 32 col-groups of 4
  for (int m0 = 0; m0 < N_; m0 += 128) {
    for (int f = tid; f < 2048; f += ATH) {
      int d = f >> 5, mm0 = (f & 31) << 2;
      int gm = m0 + mm0;
      float4 v = (gm < KTS) ? *(const float4*)(g_kT + ((size_t)bh * D_ + d) * KTS + gm)
                            : make_float4(0.f, 0.f, 0.f, 0.f);
      *(float4*)&sm.kv[d * 132 + mm0] = v;
    }
    __syncthreads();
    float acc[4][4];
#pragma unroll
    for (int i = 0; i < 4; i++)
#pragma unroll
      for (int j = 0; j < 4; j++) acc[i][j] = 0.f;
#pragma unroll 16
    for (int k = 0; k < D_; k++) {
      float4 av = *(const float4*)&sm.qT[k][qtr * 4];
      float4 bv = *(const float4*)&sm.kv[k * 132 + qtc * 4];
      float ar[4] = {av.x, av.y, av.z, av.w};
      float br[4] = {bv.x, bv.y, bv.z, bv.w};
#pragma unroll
      for (int i = 0; i < 4; i++)
#pragma unroll
        for (int j = 0; j < 4; j++) acc[i][j] += ar[i] * br[j];
    }
    const int mbase = m0 + qtc * 4;
    if (mbase <= 576) {
#pragma unroll
      for (int i = 0; i < 4; i++) {
        int r = qtr * 4 + i;
        int n = row0 + r;
        if (n > 576) n = 576;
        const unsigned char* xr = g_xdis + (size_t)n * N_;
        const unsigned char* yr = g_ydis + (size_t)n * N_;
        float vv[4];
#pragma unroll
        for (int j = 0; j < 4; j++) {
          int m = mbase + j;
          int mm = m <= 576 ? m : 576;
          vv[j] = (acc[i][j] + sm.bx[r][xr[mm]] + sm.by[r][yr[mm]]) * SCALE_;
        }
        *(float4*)&sm.S[r][mbase] = make_float4(vv[0], vv[1], vv[2], vv[3]);
      }
    }
    __syncthreads();
  }

  // ---- zero bins, load v embeddings ----
  for (int f = tid; f < ROWS * 52; f += ATH) {
    (&sm.bx[0][0])[f] = 0.f;
    (&sm.by[0][0])[f] = 0.f;
  }
  for (int f = tid; f < 400; f += ATH) ((float4*)sm.embx)[f] = ((const float4*)vxe)[f];
  for (int f = tid; f < 400; f += ATH) ((float4*)sm.emby)[f] = ((const float4*)vye)[f];
  __syncthreads();

  // ---- softmax (unnormalized) + relative-index binning ----
  for (int q = 0; q < 4; q++) {
    int r = wid * 4 + q;
    int n = row0 + r;
    int nc = n > 576 ? 576 : n;
    const unsigned char* xr = g_xdis + (size_t)nc * N_;
    const unsigned char* yr = g_ydis + (size_t)nc * N_;
    float mx = -1e30f;
    for (int m = lane; m < N_; m += 32) mx = fmaxf(mx, sm.S[r][m]);
#pragma unroll
    for (int o = 16; o; o >>= 1) mx = fmaxf(mx, __shfl_xor_sync(0xffffffffu, mx, o));
    float sum = 0.f;
    for (int m = lane; m < N_; m += 32) {
      float e = __expf(sm.S[r][m] - mx);
      sm.S[r][m] = e;
      sum += e;
      atomicAdd(&sm.bx[r][xr[m]], e);
      atomicAdd(&sm.by[r][yr[m]], e);
    }
#pragma unroll
    for (int o = 16; o; o >>= 1) sum += __shfl_xor_sync(0xffffffffu, sum, o);
    if (lane == 0) sm.rowsum[r] = sum;
  }
  __syncthreads();

  // ---- AV (two m-halves accumulate in parallel) ----
  const int half = tid >> 6;
  const int t64 = tid & 63;
  const int atr = t64 >> 4;   // 4 row groups
  const int atc = t64 & 15;   // 16 col groups of 4
  float oacc[4][4];
#pragma unroll
  for (int i = 0; i < 4; i++)
#pragma unroll
    for (int j = 0; j < 4; j++) oacc[i][j] = 0.f;

  for (int m0 = 0; m0 < N_; m0 += 128) {
    for (int f = tid; f < 2048; f += ATH) {
      int mm = f >> 4, c4 = (f & 15) << 2;
      int gm = m0 + mm;
      float4 v = (gm < N_) ? *(const float4*)(g_v + ((size_t)bh * N_ + gm) * D_ + c4)
                           : make_float4(0.f, 0.f, 0.f, 0.f);
      *(float4*)&sm.kv[mm * 68 + c4] = v;
    }
    __syncthreads();
    int mend = min(m0 + 128, N_);
    int mmid = min(m0 + 64, mend);
    int mstart = half ? mmid : m0;
    int mstop = half ? mend : mmid;
#pragma unroll 4
    for (int m = mstart; m < mstop; m++) {
      float ar[4];
#pragma unroll
      for (int i = 0; i < 4; i++) ar[i] = sm.S[atr * 4 + i][m];
      float4 bv = *(const float4*)&sm.kv[(m - m0) * 68 + atc * 4];
      float br[4] = {bv.x, bv.y, bv.z, bv.w};
#pragma unroll
      for (int i = 0; i < 4; i++)
#pragma unroll
        for (int j = 0; j < 4; j++) oacc[i][j] += ar[i] * br[j];
    }
    __syncthreads();
  }

  // ---- combine halves ----
  if (half == 1) {
#pragma unroll
    for (int i = 0; i < 4; i++) {
      *(float4*)&sm.red[atr * 4 + i][atc * 4] =
          make_float4(oacc[i][0], oacc[i][1], oacc[i][2], oacc[i][3]);
    }
  }
  __syncthreads();

  // ---- epilogue: value-path pos-bias GEMM + normalize + store ----
  if (half == 0) {
    const int b = bh / H_, h = bh % H_;
    const int c0 = atc * 4;
#pragma unroll
    for (int i = 0; i < 4; i++) {
      int r = atr * 4 + i;
      float4 oth = *(const float4*)&sm.red[r][c0];
      float o0 = oacc[i][0] + oth.x;
      float o1 = oacc[i][1] + oth.y;
      float o2 = oacc[i][2] + oth.z;
      float o3 = oacc[i][3] + oth.w;
      if (c0 < 32) {
#pragma unroll 10
        for (int t = 0; t < 50; t++) {
          float w = sm.bx[r][t];
          float4 e = *(const float4*)&sm.embx[t * 32 + c0];
          o0 += w * e.x; o1 += w * e.y; o2 += w * e.z; o3 += w * e.w;
        }
      } else {
#pragma unroll 10
        for (int t = 0; t < 50; t++) {
          float w = sm.by[r][t];
          float4 e = *(const float4*)&sm.emby[t * 32 + (c0 - 32)];
          o0 += w * e.x; o1 += w * e.y; o2 += w * e.z; o3 += w * e.w;
        }
      }
      float inv = 1.f / sm.rowsum[r];
      int n = row0 + r;
      if (n < N_) {
        *(float4*)(g_ao + ((size_t)b * N_ + n) * C_ + h * D_ + c0) =
            make_float4(o0 * inv, o1 * inv, o2 * inv, o3 * inv);
      }
    }
  }
}

// ---------------- launch ----------------
extern "C" void kernel_launch(void* const* d_in, const int* in_sizes, int n_in,
                              void* d_out, int out_size) {
  const float* x = (const float*)d_in[0];
  const float* qkv_w = (const float*)d_in[1];
  const float* proj_w = (const float*)d_in[2];
  const float* qxe = (const float*)d_in[3];
  const float* qye = (const float*)d_in[4];
  const float* vxe = (const float*)d_in[5];
  const float* vye = (const float*)d_in[6];
  float* out = (float*)d_out;

  init_dis_kernel<<<(N_ * N_ + 255) / 256, 256>>>();

  dim3 g1(3 * C_ / BN, (M_ + BM - 1) / BM);  // 18 x 73
  sgemm_kernel<0><<<g1, 256>>>(x, qkv_w, nullptr);

  cudaFuncSetAttribute(attn_kernel, cudaFuncAttributeMaxDynamicSharedMemorySize,
                       (int)sizeof(AttnSmem));
  dim3 g2((N_ + ROWS - 1) / ROWS, BH_);  // 37 x 192
  attn_kernel<<<g2, ATH, sizeof(AttnSmem)>>>(qxe, qye, vxe, vye);

  dim3 g3(C_ / BN, (M_ + BM - 1) / BM);  // 6 x 73
  sgemm_kernel<1><<<g3, 256>>>(nullptr, proj_w, out);
}

// round 2
// speedup vs baseline: 2.3651x; 2.3651x over previous
#include <cuda_runtime.h>
#include <cstdint>

#define B_ 16
#define N_ 577
#define H_ 12
#define D_ 64
#define C_ 768
#define BH_ 192
#define M_ 9232
#define KTS 640       // kT row stride (zero-padded cols 577..639)
#define SST 640       // score row stride
#define SCALE_ 0.125f

// ---------------- device scratch (no cudaMalloc allowed) ----------------
__device__ float g_q[BH_ * N_ * D_];                 // (bh, n, d)
__device__ float g_kT[BH_ * D_ * KTS];               // (bh, d, n) zero-padded
__device__ float g_v[BH_ * N_ * D_];                 // (bh, n, d)
__device__ float g_S[(size_t)BH_ * N_ * SST];        // scores, then exp(P)
__device__ float g_pxy[BH_ * N_ * 104];              // px[0:52), py[52:104)
__device__ float g_bins[BH_ * N_ * 104];             // binx[0:52), biny[52:104)
__device__ float g_rowsum[BH_ * N_];
__device__ float g_ao[M_ * C_];                      // attention out (b*n, c)

// ---------------- SGEMM: C[m,c] = sum_k A[m,k] * W[c,k] ----------------
#define BM 128
#define BN 128
#define BK 16

// MODE 0: store into g_q / g_kT / g_v (QKV projection)
// MODE 1: plain row-major store into `out` (final projection), A read from g_ao
template <int MODE>
__global__ __launch_bounds__(256)
void sgemm_kernel(const float* __restrict__ Ain, const float* __restrict__ W,
                  float* __restrict__ out) {
  __shared__ float As[BK][BM + 4];
  __shared__ float Bs[BK][BN + 4];
  const float* A = (MODE == 0) ? Ain : (const float*)g_ao;
  const int row0 = blockIdx.y * BM;
  const int col0 = blockIdx.x * BN;
  const int tid = threadIdx.x;
  const int tr = tid >> 4, tc = tid & 15;
  const int lr = tid >> 1, lk = (tid & 1) << 3;

  float acc[8][8];
#pragma unroll
  for (int i = 0; i < 8; i++)
#pragma unroll
    for (int j = 0; j < 8; j++) acc[i][j] = 0.f;

  for (int k0 = 0; k0 < C_; k0 += BK) {
    float4 a0, a1;
    int grow = row0 + lr;
    if (grow < M_) {
      const float* ap = A + (size_t)grow * C_ + k0 + lk;
      a0 = *(const float4*)ap;
      a1 = *(const float4*)(ap + 4);
    } else {
      a0 = make_float4(0.f, 0.f, 0.f, 0.f);
      a1 = a0;
    }
    const float* wp = W + (size_t)(col0 + lr) * C_ + k0 + lk;
    float4 b0 = *(const float4*)wp;
    float4 b1 = *(const float4*)(wp + 4);
    __syncthreads();
    As[lk + 0][lr] = a0.x; As[lk + 1][lr] = a0.y;
    As[lk + 2][lr] = a0.z; As[lk + 3][lr] = a0.w;
    As[lk + 4][lr] = a1.x; As[lk + 5][lr] = a1.y;
    As[lk + 6][lr] = a1.z; As[lk + 7][lr] = a1.w;
    Bs[lk + 0][lr] = b0.x; Bs[lk + 1][lr] = b0.y;
    Bs[lk + 2][lr] = b0.z; Bs[lk + 3][lr] = b0.w;
    Bs[lk + 4][lr] = b1.x; Bs[lk + 5][lr] = b1.y;
    Bs[lk + 6][lr] = b1.z; Bs[lk + 7][lr] = b1.w;
    __syncthreads();
#pragma unroll
    for (int k = 0; k < BK; k++) {
      float ar[8], br[8];
      *(float4*)&ar[0] = *(const float4*)&As[k][tr * 8];
      *(float4*)&ar[4] = *(const float4*)&As[k][tr * 8 + 4];
      *(float4*)&br[0] = *(const float4*)&Bs[k][tc * 8];
      *(float4*)&br[4] = *(const float4*)&Bs[k][tc * 8 + 4];
#pragma unroll
      for (int i = 0; i < 8; i++)
#pragma unroll
        for (int j = 0; j < 8; j++) acc[i][j] += ar[i] * br[j];
    }
  }

  const int c0 = col0 + tc * 8;
  if (MODE == 1) {
#pragma unroll
    for (int i = 0; i < 8; i++) {
      int m = row0 + tr * 8 + i;
      if (m >= M_) break;
      float* dst = out + (size_t)m * C_ + c0;
      *(float4*)dst = make_float4(acc[i][0], acc[i][1], acc[i][2], acc[i][3]);
      *(float4*)(dst + 4) = make_float4(acc[i][4], acc[i][5], acc[i][6], acc[i][7]);
    }
  } else {
    const int which = c0 / C_;         // 0=q 1=k 2=v
    const int rem = c0 % C_;
    const int h = rem / D_;
    const int d0 = rem % D_;
#pragma unroll
    for (int i = 0; i < 8; i++) {
      int m = row0 + tr * 8 + i;
      if (m >= M_) break;
      int b = m / N_, n = m % N_;
      int bh = b * H_ + h;
      if (which == 1) {
        size_t base = ((size_t)bh * D_ + d0) * KTS + n;
#pragma unroll
        for (int j = 0; j < 8; j++) g_kT[base + (size_t)j * KTS] = acc[i][j];
      } else {
        float* dst = (which == 0 ? g_q : g_v) + ((size_t)bh * N_ + n) * D_ + d0;
        *(float4*)dst = make_float4(acc[i][0], acc[i][1], acc[i][2], acc[i][3]);
        *(float4*)(dst + 4) = make_float4(acc[i][4], acc[i][5], acc[i][6], acc[i][7]);
      }
    }
  }
}

// ---------------- px/py projection: px[n,t] = q[n,0:32]·qxe[t], py = q[n,32:64]·qye[t] ----------------
__global__ __launch_bounds__(256)
void pxpy_kernel(const float* __restrict__ qxe, const float* __restrict__ qye) {
  __shared__ float qs[64][65];
  __shared__ float ex[50][33];
  __shared__ float ey[50][33];
  const int bh = blockIdx.y;
  const int row0 = blockIdx.x * 64;
  const int tid = threadIdx.x;
  for (int f = tid; f < 64 * 16; f += 256) {
    int r = f >> 4, c4 = (f & 15) << 2;
    int n = row0 + r;
    float4 v = (n < N_) ? *(const float4*)(g_q + ((size_t)bh * N_ + n) * D_ + c4)
                        : make_float4(0.f, 0.f, 0.f, 0.f);
    qs[r][c4 + 0] = v.x; qs[r][c4 + 1] = v.y;
    qs[r][c4 + 2] = v.z; qs[r][c4 + 3] = v.w;
  }
  for (int f = tid; f < 1600; f += 256) {
    ex[f >> 5][f & 31] = qxe[f];
    ey[f >> 5][f & 31] = qye[f];
  }
  __syncthreads();
  for (int idx = tid; idx < 64 * 50; idx += 256) {
    int r = idx / 50, t = idx % 50;
    float ax = 0.f, ay = 0.f;
#pragma unroll
    for (int d = 0; d < 32; d++) {
      ax += qs[r][d] * ex[t][d];
      ay += qs[r][32 + d] * ey[t][d];
    }
    int n = row0 + r;
    if (n < N_) {
      float* p = g_pxy + ((size_t)bh * N_ + n) * 104;
      p[t] = ax;
      p[52 + t] = ay;
    }
  }
}

// ---------------- scores: S[bh,n,m] = q·k (raw, no bias/scale) ----------------
__global__ __launch_bounds__(256)
void scores_kernel() {
  __shared__ float As[16][132];
  __shared__ float Bs[16][136];
  const int bh = blockIdx.z;
  const int row0 = blockIdx.y * 128;
  const int col0 = blockIdx.x * 128;
  const int tid = threadIdx.x;
  const int tr = tid >> 4, tc = tid & 15;
  const int lr = tid >> 1, lk = (tid & 1) << 3;
  const int kr = tid >> 4, kc = (tid & 15) << 3;
  const float* qb = g_q + (size_t)bh * N_ * D_;
  const float* kb = g_kT + (size_t)bh * D_ * KTS;

  float acc[8][8];
#pragma unroll
  for (int i = 0; i < 8; i++)
#pragma unroll
    for (int j = 0; j < 8; j++) acc[i][j] = 0.f;

  for (int k0 = 0; k0 < D_; k0 += 16) {
    float4 a0, a1;
    int n = row0 + lr;
    if (n < N_) {
      const float* p = qb + (size_t)n * D_ + k0 + lk;
      a0 = *(const float4*)p;
      a1 = *(const float4*)(p + 4);
    } else {
      a0 = make_float4(0.f, 0.f, 0.f, 0.f);
      a1 = a0;
    }
    const float* p2 = kb + (size_t)(k0 + kr) * KTS + col0 + kc;
    float4 b0 = *(const float4*)p2;
    float4 b1 = *(const float4*)(p2 + 4);
    __syncthreads();
    As[lk + 0][lr] = a0.x; As[lk + 1][lr] = a0.y;
    As[lk + 2][lr] = a0.z; As[lk + 3][lr] = a0.w;
    As[lk + 4][lr] = a1.x; As[lk + 5][lr] = a1.y;
    As[lk + 6][lr] = a1.z; As[lk + 7][lr] = a1.w;
    *(float4*)&Bs[kr][kc] = b0;
    *(float4*)&Bs[kr][kc + 4] = b1;
    __syncthreads();
#pragma unroll
    for (int k = 0; k < 16; k++) {
      float ar[8], br[8];
      *(float4*)&ar[0] = *(const float4*)&As[k][tr * 8];
      *(float4*)&ar[4] = *(const float4*)&As[k][tr * 8 + 4];
      *(float4*)&br[0] = *(const float4*)&Bs[k][tc * 8];
      *(float4*)&br[4] = *(const float4*)&Bs[k][tc * 8 + 4];
#pragma unroll
      for (int i = 0; i < 8; i++)
#pragma unroll
        for (int j = 0; j < 8; j++) acc[i][j] += ar[i] * br[j];
    }
  }
  float* sb = g_S + (size_t)bh * N_ * SST;
#pragma unroll
  for (int i = 0; i < 8; i++) {
    int r = row0 + tr * 8 + i;
    if (r < N_) {
      float* dst = sb + (size_t)r * SST + col0 + tc * 8;
      *(float4*)dst = make_float4(acc[i][0], acc[i][1], acc[i][2], acc[i][3]);
      *(float4*)(dst + 4) = make_float4(acc[i][4], acc[i][5], acc[i][6], acc[i][7]);
    }
  }
}

// ---------------- softmax + bias + analytic binning (one warp per row) ----------------
__global__ __launch_bounds__(256)
void softmax_kernel() {
  __shared__ float st[8][64];
  const int w = threadIdx.x >> 5, lane = threadIdx.x & 31;
  const int row = blockIdx.x * 8 + w;
  if (row >= BH_ * N_) return;
  const int n = row % N_;
  float* Srow = g_S + (size_t)row * SST;
  const float* pxy = g_pxy + (size_t)row * 104;
  const bool cls = (n == 0);
  const int xcol = cls ? 0 : (n - 1) % 24;
  const int yrow = cls ? 0 : (n - 1) / 24;

  float pxl = 0.f, pyl = 0.f;
  if (lane < 24) {
    pxl = cls ? pxy[0] : pxy[25 + lane - xcol];
    pyl = cls ? pxy[52] : pxy[52 + 25 + lane - yrow];
  }
  const float l0 = (Srow[0] + pxy[0] + pxy[52]) * SCALE_;
  float mx = l0;
  float lg[24];
#pragma unroll
  for (int k = 0; k < 24; k++) {
    float pyk = __shfl_sync(0xffffffffu, pyl, k);
    float s = -1e30f;
    if (lane < 24) s = (Srow[1 + 24 * k + lane] + pxl + pyk) * SCALE_;
    lg[k] = s;
    mx = fmaxf(mx, s);
  }
#pragma unroll
  for (int o = 16; o; o >>= 1) mx = fmaxf(mx, __shfl_xor_sync(0xffffffffu, mx, o));

  float colsum = 0.f, total = 0.f, binyreg = 0.f;
  const float e0 = __expf(l0 - mx);
#pragma unroll
  for (int k = 0; k < 24; k++) {
    float e = 0.f;
    if (lane < 24) {
      e = __expf(lg[k] - mx);
      Srow[1 + 24 * k + lane] = e;
    }
    colsum += e;
    float rs = e;
#pragma unroll
    for (int o = 16; o; o >>= 1) rs += __shfl_xor_sync(0xffffffffu, rs, o);
    total += rs;
    if (lane == k) binyreg = rs;
  }
  if (lane == 0) Srow[0] = e0;
  Srow[577 + lane] = 0.f;  // zero-pad cols 577..608 for the AV GEMM
  total += e0;
  if (lane == 0) g_rowsum[row] = total;

  st[w][lane] = colsum;
  st[w][32 + lane] = binyreg;
  __syncwarp();
  float* brow = g_bins + (size_t)row * 104;
  for (int t = lane; t < 104; t += 32) {
    float v = 0.f;
    if (cls) {
      if (t == 0 || t == 52) v = total;
    } else if (t == 0 || t == 52) {
      v = e0;
    } else if (t < 52) {
      int c = t - 25 + xcol;
      if (c >= 0 && c < 24) v = st[w][c];
    } else {
      int k = (t - 52) - 25 + yrow;
      if (k >= 0 && k < 24) v = st[w][32 + k];
    }
    brow[t] = v;
  }
}

// ---------------- AV + value-path bias + normalize ----------------
__global__ __launch_bounds__(256)
void av_kernel(const float* __restrict__ vxe, const float* __restrict__ vye) {
  __shared__ float As[16][136];
  __shared__ float Bs[16][68];
  __shared__ float ex[50][33];
  __shared__ float ey[50][33];
  const int bh = blockIdx.y;
  const int row0 = blockIdx.x * 128;
  const int tid = threadIdx.x;
  const int tr = tid >> 4, tc = tid & 15;
  const int lr = tid >> 1, lk = (tid & 1) << 3;
  const int vk = tid >> 4, vc = (tid & 15) << 2;

  for (int f = tid; f < 1600; f += 256) {
    ex[f >> 5][f & 31] = vxe[f];
    ey[f >> 5][f & 31] = vye[f];
  }
  const float* Sb = g_S + (size_t)bh * N_ * SST;
  const float* vb = g_v + (size_t)bh * N_ * D_;

  float acc[8][4];
#pragma unroll
  for (int i = 0; i < 8; i++)
#pragma unroll
    for (int j = 0; j < 4; j++) acc[i][j] = 0.f;

  for (int k0 = 0; k0 < 592; k0 += 16) {
    float4 a0, a1;
    int n = row0 + lr;
    if (n < N_) {
      const float* p = Sb + (size_t)n * SST + k0 + lk;
      a0 = *(const float4*)p;
      a1 = *(const float4*)(p + 4);
    } else {
      a0 = make_float4(0.f, 0.f, 0.f, 0.f);
      a1 = a0;
    }
    int m = k0 + vk;
    float4 b = (m < N_) ? *(const float4*)(vb + (size_t)m * D_ + vc)
                        : make_float4(0.f, 0.f, 0.f, 0.f);
    __syncthreads();
    As[lk + 0][lr] = a0.x; As[lk + 1][lr] = a0.y;
    As[lk + 2][lr] = a0.z; As[lk + 3][lr] = a0.w;
    As[lk + 4][lr] = a1.x; As[lk + 5][lr] = a1.y;
    As[lk + 6][lr] = a1.z; As[lk + 7][lr] = a1.w;
    *(float4*)&Bs[vk][vc] = b;
    __syncthreads();
#pragma unroll
    for (int k = 0; k < 16; k++) {
      float ar[8];
      *(float4*)&ar[0] = *(const float4*)&As[k][tr * 8];
      *(float4*)&ar[4] = *(const float4*)&As[k][tr * 8 + 4];
      float4 bv = *(const float4*)&Bs[k][tc * 4];
      float br[4] = {bv.x, bv.y, bv.z, bv.w};
#pragma unroll
      for (int i = 0; i < 8; i++)
#pragma unroll
        for (int j = 0; j < 4; j++) acc[i][j] += ar[i] * br[j];
    }
  }

  const int b = bh / H_, h = bh % H_;
  const int c0 = tc << 2;
  const float (*emb)[33] = (c0 < 32) ? ex : ey;
  const int ccol = (c0 < 32) ? c0 : c0 - 32;
  const int boff = (c0 < 32) ? 0 : 52;
#pragma unroll
  for (int i = 0; i < 8; i++) {
    int n = row0 + tr * 8 + i;
    if (n >= N_) continue;
    const float* brow = g_bins + ((size_t)bh * N_ + n) * 104 + boff;
    float o0 = acc[i][0], o1 = acc[i][1], o2 = acc[i][2], o3 = acc[i][3];
#pragma unroll 5
    for (int t = 0; t < 50; t++) {
      float wv = brow[t];
      o0 += wv * emb[t][ccol + 0];
      o1 += wv * emb[t][ccol + 1];
      o2 += wv * emb[t][ccol + 2];
      o3 += wv * emb[t][ccol + 3];
    }
    float inv = 1.f / g_rowsum[(size_t)bh * N_ + n];
    float* dst = g_ao + ((size_t)b * N_ + n) * C_ + h * D_ + c0;
    *(float4*)dst = make_float4(o0 * inv, o1 * inv, o2 * inv, o3 * inv);
  }
}

// ---------------- launch ----------------
extern "C" void kernel_launch(void* const* d_in, const int* in_sizes, int n_in,
                              void* d_out, int out_size) {
  const float* x = (const float*)d_in[0];
  const float* qkv_w = (const float*)d_in[1];
  const float* proj_w = (const float*)d_in[2];
  const float* qxe = (const float*)d_in[3];
  const float* qye = (const float*)d_in[4];
  const float* vxe = (const float*)d_in[5];
  const float* vye = (const float*)d_in[6];
  float* out = (float*)d_out;

  dim3 g1(3 * C_ / BN, (M_ + BM - 1) / BM);  // 18 x 73
  sgemm_kernel<0><<<g1, 256>>>(x, qkv_w, nullptr);

  pxpy_kernel<<<dim3(10, BH_), 256>>>(qxe, qye);

  scores_kernel<<<dim3(5, 5, BH_), 256>>>();

  softmax_kernel<<<(BH_ * N_ + 7) / 8, 256>>>();

  av_kernel<<<dim3(5, BH_), 256>>>(vxe, vye);

  dim3 g3(C_ / BN, (M_ + BM - 1) / BM);  // 6 x 73
  sgemm_kernel<1><<<g3, 256>>>(nullptr, proj_w, out);
}

// round 4
// speedup vs baseline: 3.7830x; 1.5995x over previous
#include <cuda_runtime.h>
#include <cstdint>

#define B_ 16
#define N_ 577
#define H_ 12
#define D_ 64
#define C_ 768
#define BH_ 192
#define M_ 9232
#define KTS 640       // kT row stride (zero-padded cols 577..639)
#define SST 640       // score row stride
#define SCALE_ 0.125f

// ---------------- device scratch (no cudaMalloc allowed) ----------------
__device__ float g_q[BH_ * N_ * D_];                 // (bh, n, d)
__device__ float g_kT[BH_ * D_ * KTS];               // (bh, d, n) zero-padded
__device__ float g_v[BH_ * N_ * D_];                 // (bh, n, d)
__device__ float g_S[(size_t)BH_ * N_ * SST];        // scores, then exp(P)
__device__ float g_pxy[BH_ * N_ * 104];              // px[0:52), py[52:104)
__device__ float g_bins[BH_ * N_ * 104];             // binx[0:52), biny[52:104)
__device__ float g_rowsum[BH_ * N_];
__device__ float g_ao[M_ * C_];                      // attention out (b*n, c)

// ---------------- tf32 helpers (base sm_103 target, no arch-a features) ---
__device__ __forceinline__ uint32_t f2tf(float f) {
  uint32_t r;
  asm("cvt.rna.tf32.f32 %0, %1;" : "=r"(r) : "f"(f));
  return r;
}
__device__ __forceinline__ void mma16n8k8(float* d, const uint32_t* a,
                                          uint32_t b0, uint32_t b1) {
  asm volatile(
      "mma.sync.aligned.m16n8k8.row.col.f32.tf32.tf32.f32 "
      "{%0,%1,%2,%3}, {%4,%5,%6,%7}, {%8,%9}, {%0,%1,%2,%3};"
      : "+f"(d[0]), "+f"(d[1]), "+f"(d[2]), "+f"(d[3])
      : "r"(a[0]), "r"(a[1]), "r"(a[2]), "r"(a[3]), "r"(b0), "r"(b1));
}

// ======== tf32 mma.sync GEMM: C[m,c] = sum_k A[m,k] * W[c,k] ========
// 128x128 CTA tile, 256 threads (8 warps, 4x2), BK=32.
// MODE 0: A = x, scatter-store into g_q / g_kT / g_v
// MODE 1: A = g_ao, row-major store into out
template <int MODE>
__global__ __launch_bounds__(256)
void mma_gemm_kernel(const float* __restrict__ Ain, const float* __restrict__ W,
                     float* __restrict__ out) {
  __shared__ uint32_t As[128][36];
  __shared__ uint32_t Bs[128][36];
  const float* A = (MODE == 0) ? Ain : (const float*)g_ao;
  const int row0 = blockIdx.y * 128, col0 = blockIdx.x * 128;
  const int tid = threadIdx.x, lane = tid & 31, wid = tid >> 5;
  const int warpM = wid & 3, warpN = wid >> 2;
  const int g = lane >> 2, tg = lane & 3;

  float acc[16][4];
#pragma unroll
  for (int i = 0; i < 16; i++)
#pragma unroll
    for (int j = 0; j < 4; j++) acc[i][j] = 0.f;

  const int lr = tid >> 1;           // 0..127
  const int lkq = (tid & 1) * 16;    // 0 / 16
  const bool aval = (row0 + lr) < M_;
  const float* ap = A + (size_t)(row0 + lr) * C_ + lkq;
  const float* bp = W + (size_t)(col0 + lr) * C_ + lkq;

  for (int k0 = 0; k0 < C_; k0 += 32) {
    __syncthreads();
#pragma unroll
    for (int i = 0; i < 4; i++) {
      float4 va = aval ? *(const float4*)(ap + k0 + i * 4)
                       : make_float4(0.f, 0.f, 0.f, 0.f);
      float4 vb = *(const float4*)(bp + k0 + i * 4);
      uint4 ua = make_uint4(f2tf(va.x), f2tf(va.y), f2tf(va.z), f2tf(va.w));
      uint4 ub = make_uint4(f2tf(vb.x), f2tf(vb.y), f2tf(vb.z), f2tf(vb.w));
      *(uint4*)&As[lr][lkq + i * 4] = ua;
      *(uint4*)&Bs[lr][lkq + i * 4] = ub;
    }
    __syncthreads();
#pragma unroll
    for (int s = 0; s < 4; s++) {
      const int kk = s * 8;
      uint32_t a[2][4];
#pragma unroll
      for (int mt = 0; mt < 2; mt++) {
        const int r = warpM * 32 + mt * 16;
        a[mt][0] = As[r + g][kk + tg];
        a[mt][1] = As[r + g + 8][kk + tg];
        a[mt][2] = As[r + g][kk + tg + 4];
        a[mt][3] = As[r + g + 8][kk + tg + 4];
      }
#pragma unroll
      for (int nt = 0; nt < 8; nt++) {
        const int c = warpN * 64 + nt * 8;
        uint32_t b0 = Bs[c + g][kk + tg];
        uint32_t b1 = Bs[c + g][kk + tg + 4];
        mma16n8k8(acc[nt], a[0], b0, b1);
        mma16n8k8(acc[8 + nt], a[1], b0, b1);
      }
    }
  }

  // ---- epilogue ----
  // thread's c-values: rows m = row0+warpM*32+mt*16+g (c0,c1) / +8 (c2,c3)
  //                    cols cb = col0+warpN*64+nt*8+2*tg (+0,+1)
  if (MODE == 1) {
#pragma unroll
    for (int mt = 0; mt < 2; mt++)
#pragma unroll
      for (int half = 0; half < 2; half++) {
        const int m = row0 + warpM * 32 + mt * 16 + g + half * 8;
        if (m >= M_) continue;
        float* dst = out + (size_t)m * C_ + col0 + warpN * 64 + 2 * tg;
#pragma unroll
        for (int nt = 0; nt < 8; nt++) {
          float2 v = make_float2(acc[mt * 8 + nt][half * 2],
                                 acc[mt * 8 + nt][half * 2 + 1]);
          *(float2*)(dst + nt * 8) = v;
        }
      }
  } else {
    const int cg = col0 + warpN * 64;   // multiple of 64 -> one head per warp
    const int which = cg / C_;          // 0=q 1=k 2=v
    const int h = (cg % C_) / D_;
#pragma unroll
    for (int mt = 0; mt < 2; mt++)
#pragma unroll
      for (int half = 0; half < 2; half++) {
        const int m = row0 + warpM * 32 + mt * 16 + g + half * 8;
        if (m >= M_) continue;
        const int b = m / N_, n = m % N_;
        const int bh = b * H_ + h;
        if (which == 1) {
          const size_t base = (size_t)bh * D_ * KTS + n;
          const int d0 = 2 * tg;
#pragma unroll
          for (int nt = 0; nt < 8; nt++) {
            g_kT[base + (size_t)(d0 + nt * 8) * KTS] = acc[mt * 8 + nt][half * 2];
            g_kT[base + (size_t)(d0 + nt * 8 + 1) * KTS] =
                acc[mt * 8 + nt][half * 2 + 1];
          }
        } else {
          float* dst = (which == 0 ? g_q : g_v) + ((size_t)bh * N_ + n) * D_ + 2 * tg;
#pragma unroll
          for (int nt = 0; nt < 8; nt++) {
            float2 v = make_float2(acc[mt * 8 + nt][half * 2],
                                   acc[mt * 8 + nt][half * 2 + 1]);
            *(float2*)(dst + nt * 8) = v;
          }
        }
      }
  }
}

// ---------------- px/py projection ----------------
__global__ __launch_bounds__(256)
void pxpy_kernel(const float* __restrict__ qxe, const float* __restrict__ qye) {
  __shared__ float qs[64][65];
  __shared__ float ex[50][33];
  __shared__ float ey[50][33];
  const int bh = blockIdx.y;
  const int row0 = blockIdx.x * 64;
  const int tid = threadIdx.x;
  for (int f = tid; f < 64 * 16; f += 256) {
    int r = f >> 4, c4 = (f & 15) << 2;
    int n = row0 + r;
    float4 v = (n < N_) ? *(const float4*)(g_q + ((size_t)bh * N_ + n) * D_ + c4)
                        : make_float4(0.f, 0.f, 0.f, 0.f);
    qs[r][c4 + 0] = v.x; qs[r][c4 + 1] = v.y;
    qs[r][c4 + 2] = v.z; qs[r][c4 + 3] = v.w;
  }
  for (int f = tid; f < 1600; f += 256) {
    ex[f >> 5][f & 31] = qxe[f];
    ey[f >> 5][f & 31] = qye[f];
  }
  __syncthreads();
  for (int idx = tid; idx < 64 * 50; idx += 256) {
    int r = idx / 50, t = idx % 50;
    float ax = 0.f, ay = 0.f;
#pragma unroll
    for (int d = 0; d < 32; d++) {
      ax += qs[r][d] * ex[t][d];
      ay += qs[r][32 + d] * ey[t][d];
    }
    int n = row0 + r;
    if (n < N_) {
      float* p = g_pxy + ((size_t)bh * N_ + n) * 104;
      p[t] = ax;
      p[52 + t] = ay;
    }
  }
}

// ---------------- scores: S[bh,n,m] = q·k (raw) ----------------
__global__ __launch_bounds__(256)
void scores_kernel() {
  __shared__ float As[16][132];
  __shared__ float Bs[16][136];
  const int bh = blockIdx.z;
  const int row0 = blockIdx.y * 128;
  const int col0 = blockIdx.x * 128;
  const int tid = threadIdx.x;
  const int tr = tid >> 4, tc = tid & 15;
  const int lr = tid >> 1, lk = (tid & 1) << 3;
  const int kr = tid >> 4, kc = (tid & 15) << 3;
  const float* qb = g_q + (size_t)bh * N_ * D_;
  const float* kb = g_kT + (size_t)bh * D_ * KTS;

  float acc[8][8];
#pragma unroll
  for (int i = 0; i < 8; i++)
#pragma unroll
    for (int j = 0; j < 8; j++) acc[i][j] = 0.f;

  for (int k0 = 0; k0 < D_; k0 += 16) {
    float4 a0, a1;
    int n = row0 + lr;
    if (n < N_) {
      const float* p = qb + (size_t)n * D_ + k0 + lk;
      a0 = *(const float4*)p;
      a1 = *(const float4*)(p + 4);
    } else {
      a0 = make_float4(0.f, 0.f, 0.f, 0.f);
      a1 = a0;
    }
    const float* p2 = kb + (size_t)(k0 + kr) * KTS + col0 + kc;
    float4 b0 = *(const float4*)p2;
    float4 b1 = *(const float4*)(p2 + 4);
    __syncthreads();
    As[lk + 0][lr] = a0.x; As[lk + 1][lr] = a0.y;
    As[lk + 2][lr] = a0.z; As[lk + 3][lr] = a0.w;
    As[lk + 4][lr] = a1.x; As[lk + 5][lr] = a1.y;
    As[lk + 6][lr] = a1.z; As[lk + 7][lr] = a1.w;
    *(float4*)&Bs[kr][kc] = b0;
    *(float4*)&Bs[kr][kc + 4] = b1;
    __syncthreads();
#pragma unroll
    for (int k = 0; k < 16; k++) {
      float ar[8], br[8];
      *(float4*)&ar[0] = *(const float4*)&As[k][tr * 8];
      *(float4*)&ar[4] = *(const float4*)&As[k][tr * 8 + 4];
      *(float4*)&br[0] = *(const float4*)&Bs[k][tc * 8];
      *(float4*)&br[4] = *(const float4*)&Bs[k][tc * 8 + 4];
#pragma unroll
      for (int i = 0; i < 8; i++)
#pragma unroll
        for (int j = 0; j < 8; j++) acc[i][j] += ar[i] * br[j];
    }
  }
  float* sb = g_S + (size_t)bh * N_ * SST;
#pragma unroll
  for (int i = 0; i < 8; i++) {
    int r = row0 + tr * 8 + i;
    if (r < N_) {
      float* dst = sb + (size_t)r * SST + col0 + tc * 8;
      *(float4*)dst = make_float4(acc[i][0], acc[i][1], acc[i][2], acc[i][3]);
      *(float4*)(dst + 4) = make_float4(acc[i][4], acc[i][5], acc[i][6], acc[i][7]);
    }
  }
}

// ---------------- softmax + bias + analytic binning ----------------
__global__ __launch_bounds__(256)
void softmax_kernel() {
  __shared__ float st[8][64];
  const int w = threadIdx.x >> 5, lane = threadIdx.x & 31;
  const int row = blockIdx.x * 8 + w;
  if (row >= BH_ * N_) return;
  const int n = row % N_;
  float* Srow = g_S + (size_t)row * SST;
  const float* pxy = g_pxy + (size_t)row * 104;
  const bool cls = (n == 0);
  const int xcol = cls ? 0 : (n - 1) % 24;
  const int yrow = cls ? 0 : (n - 1) / 24;

  float pxl = 0.f, pyl = 0.f;
  if (lane < 24) {
    pxl = cls ? pxy[0] : pxy[25 + lane - xcol];
    pyl = cls ? pxy[52] : pxy[52 + 25 + lane - yrow];
  }
  const float l0 = (Srow[0] + pxy[0] + pxy[52]) * SCALE_;
  float mx = l0;
  float lg[24];
#pragma unroll
  for (int k = 0; k < 24; k++) {
    float pyk = __shfl_sync(0xffffffffu, pyl, k);
    float s = -1e30f;
    if (lane < 24) s = (Srow[1 + 24 * k + lane] + pxl + pyk) * SCALE_;
    lg[k] = s;
    mx = fmaxf(mx, s);
  }
#pragma unroll
  for (int o = 16; o; o >>= 1) mx = fmaxf(mx, __shfl_xor_sync(0xffffffffu, mx, o));

  float colsum = 0.f, total = 0.f, binyreg = 0.f;
  const float e0 = __expf(l0 - mx);
#pragma unroll
  for (int k = 0; k < 24; k++) {
    float e = 0.f;
    if (lane < 24) {
      e = __expf(lg[k] - mx);
      Srow[1 + 24 * k + lane] = e;
    }
    colsum += e;
    float rs = e;
#pragma unroll
    for (int o = 16; o; o >>= 1) rs += __shfl_xor_sync(0xffffffffu, rs, o);
    total += rs;
    if (lane == k) binyreg = rs;
  }
  if (lane == 0) Srow[0] = e0;
  Srow[577 + lane] = 0.f;
  total += e0;
  if (lane == 0) g_rowsum[row] = total;

  st[w][lane] = colsum;
  st[w][32 + lane] = binyreg;
  __syncwarp();
  float* brow = g_bins + (size_t)row * 104;
  for (int t = lane; t < 104; t += 32) {
    float v = 0.f;
    if (cls) {
      if (t == 0 || t == 52) v = total;
    } else if (t == 0 || t == 52) {
      v = e0;
    } else if (t < 52) {
      int c = t - 25 + xcol;
      if (c >= 0 && c < 24) v = st[w][c];
    } else {
      int k = (t - 52) - 25 + yrow;
      if (k >= 0 && k < 24) v = st[w][32 + k];
    }
    brow[t] = v;
  }
}

// ---------------- AV + value-path bias + normalize ----------------
__global__ __launch_bounds__(256)
void av_kernel(const float* __restrict__ vxe, const float* __restrict__ vye) {
  __shared__ float As[16][136];
  __shared__ float Bs[16][68];
  __shared__ float ex[50][33];
  __shared__ float ey[50][33];
  const int bh = blockIdx.y;
  const int row0 = blockIdx.x * 128;
  const int tid = threadIdx.x;
  const int tr = tid >> 4, tc = tid & 15;
  const int lr = tid >> 1, lk = (tid & 1) << 3;
  const int vk = tid >> 4, vc = (tid & 15) << 2;

  for (int f = tid; f < 1600; f += 256) {
    ex[f >> 5][f & 31] = vxe[f];
    ey[f >> 5][f & 31] = vye[f];
  }
  const float* Sb = g_S + (size_t)bh * N_ * SST;
  const float* vb = g_v + (size_t)bh * N_ * D_;

  float acc[8][4];
#pragma unroll
  for (int i = 0; i < 8; i++)
#pragma unroll
    for (int j = 0; j < 4; j++) acc[i][j] = 0.f;

  for (int k0 = 0; k0 < 592; k0 += 16) {
    float4 a0, a1;
    int n = row0 + lr;
    if (n < N_) {
      const float* p = Sb + (size_t)n * SST + k0 + lk;
      a0 = *(const float4*)p;
      a1 = *(const float4*)(p + 4);
    } else {
      a0 = make_float4(0.f, 0.f, 0.f, 0.f);
      a1 = a0;
    }
    int m = k0 + vk;
    float4 b = (m < N_) ? *(const float4*)(vb + (size_t)m * D_ + vc)
                        : make_float4(0.f, 0.f, 0.f, 0.f);
    __syncthreads();
    As[lk + 0][lr] = a0.x; As[lk + 1][lr] = a0.y;
    As[lk + 2][lr] = a0.z; As[lk + 3][lr] = a0.w;
    As[lk + 4][lr] = a1.x; As[lk + 5][lr] = a1.y;
    As[lk + 6][lr] = a1.z; As[lk + 7][lr] = a1.w;
    *(float4*)&Bs[vk][vc] = b;
    __syncthreads();
#pragma unroll
    for (int k = 0; k < 16; k++) {
      float ar[8];
      *(float4*)&ar[0] = *(const float4*)&As[k][tr * 8];
      *(float4*)&ar[4] = *(const float4*)&As[k][tr * 8 + 4];
      float4 bv = *(const float4*)&Bs[k][tc * 4];
      float br[4] = {bv.x, bv.y, bv.z, bv.w};
#pragma unroll
      for (int i = 0; i < 8; i++)
#pragma unroll
        for (int j = 0; j < 4; j++) acc[i][j] += ar[i] * br[j];
    }
  }

  const int b = bh / H_, h = bh % H_;
  const int c0 = tc << 2;
  const float (*emb)[33] = (c0 < 32) ? ex : ey;
  const int ccol = (c0 < 32) ? c0 : c0 - 32;
  const int boff = (c0 < 32) ? 0 : 52;
#pragma unroll
  for (int i = 0; i < 8; i++) {
    int n = row0 + tr * 8 + i;
    if (n >= N_) continue;
    const float* brow = g_bins + ((size_t)bh * N_ + n) * 104 + boff;
    float o0 = acc[i][0], o1 = acc[i][1], o2 = acc[i][2], o3 = acc[i][3];
#pragma unroll 5
    for (int t = 0; t < 50; t++) {
      float wv = brow[t];
      o0 += wv * emb[t][ccol + 0];
      o1 += wv * emb[t][ccol + 1];
      o2 += wv * emb[t][ccol + 2];
      o3 += wv * emb[t][ccol + 3];
    }
    float inv = 1.f / g_rowsum[(size_t)bh * N_ + n];
    float* dst = g_ao + ((size_t)b * N_ + n) * C_ + h * D_ + c0;
    *(float4*)dst = make_float4(o0 * inv, o1 * inv, o2 * inv, o3 * inv);
  }
}

// ---------------- launch ----------------
extern "C" void kernel_launch(void* const* d_in, const int* in_sizes, int n_in,
                              void* d_out, int out_size) {
  const float* x = (const float*)d_in[0];
  const float* qkv_w = (const float*)d_in[1];
  const float* proj_w = (const float*)d_in[2];
  const float* qxe = (const float*)d_in[3];
  const float* qye = (const float*)d_in[4];
  const float* vxe = (const float*)d_in[5];
  const float* vye = (const float*)d_in[6];
  float* out = (float*)d_out;

  // QKV projection (tf32 tensor cores): (9232 x 768) @ (2304 x 768)^T
  mma_gemm_kernel<0><<<dim3(18, 73), 256>>>(x, qkv_w, nullptr);

  pxpy_kernel<<<dim3(10, BH_), 256>>>(qxe, qye);

  scores_kernel<<<dim3(5, 5, BH_), 256>>>();

  softmax_kernel<<<(BH_ * N_ + 7) / 8, 256>>>();

  av_kernel<<<dim3(5, BH_), 256>>>(vxe, vye);

  // Output projection (tf32 tensor cores): (9232 x 768) @ (768 x 768)^T
  mma_gemm_kernel<1><<<dim3(6, 73), 256>>>(nullptr, proj_w, out);
}

// round 5
// speedup vs baseline: 4.5565x; 1.2044x over previous
#include <cuda_runtime.h>
#include <cstdint>

#define B_ 16
#define N_ 577
#define H_ 12
#define D_ 64
#define C_ 768
#define BH_ 192
#define M_ 9232
#define KTS 640       // vT row stride (zero-padded cols 577..639)
#define SST 640       // score row stride
#define SCALE_ 0.125f

// ---------------- device scratch (no cudaMalloc allowed) ----------------
__device__ float g_q[BH_ * N_ * D_];                 // (bh, n, d)
__device__ float g_k[BH_ * N_ * D_];                 // (bh, n, d)
__device__ float g_vT[BH_ * D_ * KTS];               // (bh, d, m) zero-padded
__device__ float g_S[(size_t)(BH_ * N_ + 64) * SST]; // scores, then exp(P)
__device__ float g_pxy[BH_ * N_ * 104];              // px[0:52), py[52:104)
__device__ float g_bins[BH_ * N_ * 104];             // binx[0:52), biny[52:104)
__device__ float g_rowsum[BH_ * N_ + 64];
__device__ float g_ao[M_ * C_];                      // attention out (b*n, c)

// ---------------- tf32 helpers (base sm_103 target) ----------------
__device__ __forceinline__ uint32_t f2tf(float f) {
  uint32_t r;
  asm("cvt.rna.tf32.f32 %0, %1;" : "=r"(r) : "f"(f));
  return r;
}
__device__ __forceinline__ void mma16n8k8(float* d, const uint32_t* a,
                                          uint32_t b0, uint32_t b1) {
  asm volatile(
      "mma.sync.aligned.m16n8k8.row.col.f32.tf32.tf32.f32 "
      "{%0,%1,%2,%3}, {%4,%5,%6,%7}, {%8,%9}, {%0,%1,%2,%3};"
      : "+f"(d[0]), "+f"(d[1]), "+f"(d[2]), "+f"(d[3])
      : "r"(a[0]), "r"(a[1]), "r"(a[2]), "r"(a[3]), "r"(b0), "r"(b1));
}

// ======== tf32 mma.sync GEMM: C[m,c] = sum_k A[m,k] * W[c,k] ========
// MODE 0: A = x, scatter-store q/k natural + vT transposed
// MODE 1: A = g_ao, row-major store into out
template <int MODE>
__global__ __launch_bounds__(256)
void mma_gemm_kernel(const float* __restrict__ Ain, const float* __restrict__ W,
                     float* __restrict__ out) {
  __shared__ uint32_t As[128][36];
  __shared__ uint32_t Bs[128][36];
  const float* A = (MODE == 0) ? Ain : (const float*)g_ao;
  const int row0 = blockIdx.y * 128, col0 = blockIdx.x * 128;
  const int tid = threadIdx.x, lane = tid & 31, wid = tid >> 5;
  const int warpM = wid & 3, warpN = wid >> 2;
  const int g = lane >> 2, tg = lane & 3;

  float acc[16][4];
#pragma unroll
  for (int i = 0; i < 16; i++)
#pragma unroll
    for (int j = 0; j < 4; j++) acc[i][j] = 0.f;

  const int lr = tid >> 1;
  const int lkq = (tid & 1) * 16;
  const bool aval = (row0 + lr) < M_;
  const float* ap = A + (size_t)(row0 + lr) * C_ + lkq;
  const float* bp = W + (size_t)(col0 + lr) * C_ + lkq;

  for (int k0 = 0; k0 < C_; k0 += 32) {
    __syncthreads();
#pragma unroll
    for (int i = 0; i < 4; i++) {
      float4 va = aval ? *(const float4*)(ap + k0 + i * 4)
                       : make_float4(0.f, 0.f, 0.f, 0.f);
      float4 vb = *(const float4*)(bp + k0 + i * 4);
      *(uint4*)&As[lr][lkq + i * 4] =
          make_uint4(f2tf(va.x), f2tf(va.y), f2tf(va.z), f2tf(va.w));
      *(uint4*)&Bs[lr][lkq + i * 4] =
          make_uint4(f2tf(vb.x), f2tf(vb.y), f2tf(vb.z), f2tf(vb.w));
    }
    __syncthreads();
#pragma unroll
    for (int s = 0; s < 4; s++) {
      const int kk = s * 8;
      uint32_t a[2][4];
#pragma unroll
      for (int mt = 0; mt < 2; mt++) {
        const int r = warpM * 32 + mt * 16;
        a[mt][0] = As[r + g][kk + tg];
        a[mt][1] = As[r + g + 8][kk + tg];
        a[mt][2] = As[r + g][kk + tg + 4];
        a[mt][3] = As[r + g + 8][kk + tg + 4];
      }
#pragma unroll
      for (int nt = 0; nt < 8; nt++) {
        const int c = warpN * 64 + nt * 8;
        uint32_t b0 = Bs[c + g][kk + tg];
        uint32_t b1 = Bs[c + g][kk + tg + 4];
        mma16n8k8(acc[nt], a[0], b0, b1);
        mma16n8k8(acc[8 + nt], a[1], b0, b1);
      }
    }
  }

  if (MODE == 1) {
#pragma unroll
    for (int mt = 0; mt < 2; mt++)
#pragma unroll
      for (int half = 0; half < 2; half++) {
        const int m = row0 + warpM * 32 + mt * 16 + g + half * 8;
        if (m >= M_) continue;
        float* dst = out + (size_t)m * C_ + col0 + warpN * 64 + 2 * tg;
#pragma unroll
        for (int nt = 0; nt < 8; nt++)
          *(float2*)(dst + nt * 8) = make_float2(acc[mt * 8 + nt][half * 2],
                                                 acc[mt * 8 + nt][half * 2 + 1]);
      }
  } else {
    const int cg = col0 + warpN * 64;   // multiple of 64 -> one head per warp
    const int which = cg / C_;          // 0=q 1=k 2=v
    const int h = (cg % C_) / D_;
#pragma unroll
    for (int mt = 0; mt < 2; mt++)
#pragma unroll
      for (int half = 0; half < 2; half++) {
        const int m = row0 + warpM * 32 + mt * 16 + g + half * 8;
        if (m >= M_) continue;
        const int b = m / N_, n = m % N_;
        const int bh = b * H_ + h;
        if (which == 2) {
          const size_t base = (size_t)bh * D_ * KTS + n;
          const int d0 = 2 * tg;
#pragma unroll
          for (int nt = 0; nt < 8; nt++) {
            g_vT[base + (size_t)(d0 + nt * 8) * KTS] = acc[mt * 8 + nt][half * 2];
            g_vT[base + (size_t)(d0 + nt * 8 + 1) * KTS] =
                acc[mt * 8 + nt][half * 2 + 1];
          }
        } else {
          float* dst = (which == 0 ? g_q : g_k) + ((size_t)bh * N_ + n) * D_ + 2 * tg;
#pragma unroll
          for (int nt = 0; nt < 8; nt++)
            *(float2*)(dst + nt * 8) =
                make_float2(acc[mt * 8 + nt][half * 2],
                            acc[mt * 8 + nt][half * 2 + 1]);
        }
      }
  }
}

// ---------------- px/py projection ----------------
__global__ __launch_bounds__(256)
void pxpy_kernel(const float* __restrict__ qxe, const float* __restrict__ qye) {
  __shared__ float qs[64][65];
  __shared__ float ex[50][33];
  __shared__ float ey[50][33];
  const int bh = blockIdx.y;
  const int row0 = blockIdx.x * 64;
  const int tid = threadIdx.x;
  for (int f = tid; f < 64 * 16; f += 256) {
    int r = f >> 4, c4 = (f & 15) << 2;
    int n = row0 + r;
    float4 v = (n < N_) ? *(const float4*)(g_q + ((size_t)bh * N_ + n) * D_ + c4)
                        : make_float4(0.f, 0.f, 0.f, 0.f);
    qs[r][c4 + 0] = v.x; qs[r][c4 + 1] = v.y;
    qs[r][c4 + 2] = v.z; qs[r][c4 + 3] = v.w;
  }
  for (int f = tid; f < 1600; f += 256) {
    ex[f >> 5][f & 31] = qxe[f];
    ey[f >> 5][f & 31] = qye[f];
  }
  __syncthreads();
  for (int idx = tid; idx < 64 * 50; idx += 256) {
    int r = idx / 50, t = idx % 50;
    float ax = 0.f, ay = 0.f;
#pragma unroll
    for (int d = 0; d < 32; d++) {
      ax += qs[r][d] * ex[t][d];
      ay += qs[r][32 + d] * ey[t][d];
    }
    int n = row0 + r;
    if (n < N_) {
      float* p = g_pxy + ((size_t)bh * N_ + n) * 104;
      p[t] = ax;
      p[52 + t] = ay;
    }
  }
}

// ---------------- scores via mma: S[bh,n,m] = q·k ----------------
__global__ __launch_bounds__(256)
void scores_mma_kernel() {
  __shared__ uint32_t As[128][36];
  __shared__ uint32_t Bs[128][36];
  const int bh = blockIdx.z;
  const int row0 = blockIdx.y * 128, col0 = blockIdx.x * 128;
  const int tid = threadIdx.x, lane = tid & 31, wid = tid >> 5;
  const int warpM = wid & 3, warpN = wid >> 2;
  const int g = lane >> 2, tg = lane & 3;

  float acc[16][4];
#pragma unroll
  for (int i = 0; i < 16; i++)
#pragma unroll
    for (int j = 0; j < 4; j++) acc[i][j] = 0.f;

  const int lr = tid >> 1;
  const int lkq = (tid & 1) * 16;
  const bool aval = (row0 + lr) < N_;
  const bool bval = (col0 + lr) < N_;
  const float* ap = g_q + ((size_t)bh * N_ + row0 + lr) * D_ + lkq;
  const float* bp = g_k + ((size_t)bh * N_ + col0 + lr) * D_ + lkq;

  for (int k0 = 0; k0 < 64; k0 += 32) {
    __syncthreads();
#pragma unroll
    for (int i = 0; i < 4; i++) {
      float4 va = aval ? *(const float4*)(ap + k0 + i * 4)
                       : make_float4(0.f, 0.f, 0.f, 0.f);
      float4 vb = bval ? *(const float4*)(bp + k0 + i * 4)
                       : make_float4(0.f, 0.f, 0.f, 0.f);
      *(uint4*)&As[lr][lkq + i * 4] =
          make_uint4(f2tf(va.x), f2tf(va.y), f2tf(va.z), f2tf(va.w));
      *(uint4*)&Bs[lr][lkq + i * 4] =
          make_uint4(f2tf(vb.x), f2tf(vb.y), f2tf(vb.z), f2tf(vb.w));
    }
    __syncthreads();
#pragma unroll
    for (int s = 0; s < 4; s++) {
      const int kk = s * 8;
      uint32_t a[2][4];
#pragma unroll
      for (int mt = 0; mt < 2; mt++) {
        const int r = warpM * 32 + mt * 16;
        a[mt][0] = As[r + g][kk + tg];
        a[mt][1] = As[r + g + 8][kk + tg];
        a[mt][2] = As[r + g][kk + tg + 4];
        a[mt][3] = As[r + g + 8][kk + tg + 4];
      }
#pragma unroll
      for (int nt = 0; nt < 8; nt++) {
        const int c = warpN * 64 + nt * 8;
        uint32_t b0 = Bs[c + g][kk + tg];
        uint32_t b1 = Bs[c + g][kk + tg + 4];
        mma16n8k8(acc[nt], a[0], b0, b1);
        mma16n8k8(acc[8 + nt], a[1], b0, b1);
      }
    }
  }

#pragma unroll
  for (int mt = 0; mt < 2; mt++)
#pragma unroll
    for (int half = 0; half < 2; half++) {
      const int n = row0 + warpM * 32 + mt * 16 + g + half * 8;
      if (n >= N_) continue;
      float* dst = g_S + ((size_t)bh * N_ + n) * SST + col0 + warpN * 64 + 2 * tg;
#pragma unroll
      for (int nt = 0; nt < 8; nt++)
        *(float2*)(dst + nt * 8) = make_float2(acc[mt * 8 + nt][half * 2],
                                               acc[mt * 8 + nt][half * 2 + 1]);
    }
}

// ---------------- softmax + bias + analytic binning ----------------
__global__ __launch_bounds__(256)
void softmax_kernel() {
  __shared__ float st[8][64];
  const int w = threadIdx.x >> 5, lane = threadIdx.x & 31;
  const int row = blockIdx.x * 8 + w;
  if (row >= BH_ * N_) return;
  const int n = row % N_;
  float* Srow = g_S + (size_t)row * SST;
  const float* pxy = g_pxy + (size_t)row * 104;
  const bool cls = (n == 0);
  const int xcol = cls ? 0 : (n - 1) % 24;
  const int yrow = cls ? 0 : (n - 1) / 24;

  float pxl = 0.f, pyl = 0.f;
  if (lane < 24) {
    pxl = cls ? pxy[0] : pxy[25 + lane - xcol];
    pyl = cls ? pxy[52] : pxy[52 + 25 + lane - yrow];
  }
  const float l0 = (Srow[0] + pxy[0] + pxy[52]) * SCALE_;
  float mx = l0;
  float lg[24];
#pragma unroll
  for (int k = 0; k < 24; k++) {
    float pyk = __shfl_sync(0xffffffffu, pyl, k);
    float s = -1e30f;
    if (lane < 24) s = (Srow[1 + 24 * k + lane] + pxl + pyk) * SCALE_;
    lg[k] = s;
    mx = fmaxf(mx, s);
  }
#pragma unroll
  for (int o = 16; o; o >>= 1) mx = fmaxf(mx, __shfl_xor_sync(0xffffffffu, mx, o));

  float colsum = 0.f, total = 0.f, binyreg = 0.f;
  const float e0 = __expf(l0 - mx);
#pragma unroll
  for (int k = 0; k < 24; k++) {
    float e = 0.f;
    if (lane < 24) {
      e = __expf(lg[k] - mx);
      Srow[1 + 24 * k + lane] = e;
    }
    colsum += e;
    float rs = e;
#pragma unroll
    for (int o = 16; o; o >>= 1) rs += __shfl_xor_sync(0xffffffffu, rs, o);
    total += rs;
    if (lane == k) binyreg = rs;
  }
  if (lane == 0) Srow[0] = e0;
  Srow[577 + lane] = 0.f;  // zero-pad cols 577..608 for the AV mma
  total += e0;
  if (lane == 0) g_rowsum[row] = total;

  st[w][lane] = colsum;
  st[w][32 + lane] = binyreg;
  __syncwarp();
  float* brow = g_bins + (size_t)row * 104;
  for (int t = lane; t < 104; t += 32) {
    float v = 0.f;
    if (cls) {
      if (t == 0 || t == 52) v = total;
    } else if (t == 0 || t == 52) {
      v = e0;
    } else if (t < 52) {
      int c = t - 25 + xcol;
      if (c >= 0 && c < 24) v = st[w][c];
    } else {
      int k = (t - 52) - 25 + yrow;
      if (k >= 0 && k < 24) v = st[w][32 + k];
    }
    brow[t] = v;
  }
}

// ---------------- AV via mma + bias-mma + normalize ----------------
// CTA: 128 rows x 64 cols. 8 warps, each 16 rows x 64 cols.
#define AV_SMEM 77312
__global__ __launch_bounds__(256)
void av_mma_kernel(const float* __restrict__ vxe, const float* __restrict__ vye) {
  extern __shared__ uint32_t dsm[];
  uint32_t(*As)[36] = (uint32_t(*)[36])dsm;              // P tile 128x32
  uint32_t(*Bs)[36] = (uint32_t(*)[36])(dsm + 128 * 36); // vT tile 64x32
  const int bh = blockIdx.y, row0 = blockIdx.x * 128;
  const int tid = threadIdx.x, lane = tid & 31, wid = tid >> 5;
  const int g = lane >> 2, tg = lane & 3;

  float acc[8][4];
#pragma unroll
  for (int i = 0; i < 8; i++)
#pragma unroll
    for (int j = 0; j < 4; j++) acc[i][j] = 0.f;

  const int lr = tid >> 1, lk = (tid & 1) * 16;
  const float* ap = g_S + ((size_t)bh * N_ + row0 + lr) * SST + lk;
  const int vr = tid >> 2, vc = (tid & 3) * 8;
  const float* vp = g_vT + (size_t)bh * D_ * KTS + (size_t)vr * KTS + vc;
  const int wr = wid * 16;

  for (int k0 = 0; k0 < 608; k0 += 32) {
    __syncthreads();
#pragma unroll
    for (int i = 0; i < 4; i++) {
      float4 va = *(const float4*)(ap + k0 + i * 4);
      *(uint4*)&As[lr][lk + i * 4] =
          make_uint4(f2tf(va.x), f2tf(va.y), f2tf(va.z), f2tf(va.w));
    }
#pragma unroll
    for (int i = 0; i < 2; i++) {
      float4 vb = *(const float4*)(vp + k0 + i * 4);
      *(uint4*)&Bs[vr][vc + i * 4] =
          make_uint4(f2tf(vb.x), f2tf(vb.y), f2tf(vb.z), f2tf(vb.w));
    }
    __syncthreads();
#pragma unroll
    for (int s = 0; s < 4; s++) {
      const int kk = s * 8;
      uint32_t a[4];
      a[0] = As[wr + g][kk + tg];
      a[1] = As[wr + g + 8][kk + tg];
      a[2] = As[wr + g][kk + tg + 4];
      a[3] = As[wr + g + 8][kk + tg + 4];
#pragma unroll
      for (int nt = 0; nt < 8; nt++) {
        uint32_t b0 = Bs[nt * 8 + g][kk + tg];
        uint32_t b1 = Bs[nt * 8 + g][kk + tg + 4];
        mma16n8k8(acc[nt], a, b0, b1);
      }
    }
  }
  __syncthreads();

  // ---- bias phase: bins (128x52) x emb^T (32x52) accumulated via mma ----
  uint32_t* bxs = dsm;                         // [128][60]
  uint32_t* bys = dsm + 128 * 60;              // [128][60]
  uint32_t* exs = dsm + 2 * 128 * 60;          // [32][60]
  uint32_t* eys = dsm + 2 * 128 * 60 + 32 * 60;
  float* invs = (float*)(dsm + 2 * 128 * 60 + 2 * 32 * 60);  // [128]

  for (int f = tid; f < 128 * 60; f += 256) {
    int r = f / 60, t = f % 60;
    int n = row0 + r;
    float vx = 0.f, vy = 0.f;
    if (t < 52 && n < N_) {
      const float* p = g_bins + ((size_t)bh * N_ + n) * 104;
      vx = p[t];
      vy = p[52 + t];
    }
    bxs[r * 60 + t] = f2tf(vx);
    bys[r * 60 + t] = f2tf(vy);
  }
  for (int f = tid; f < 32 * 60; f += 256) {
    int c = f / 60, t = f % 60;
    float ax = 0.f, ay = 0.f;
    if (t < 50) {
      ax = vxe[t * 32 + c];
      ay = vye[t * 32 + c];
    }
    exs[f] = f2tf(ax);
    eys[f] = f2tf(ay);
  }
  for (int f = tid; f < 128; f += 256) {
    int n = row0 + f;
    invs[f] = (n < N_) ? 1.f / g_rowsum[(size_t)bh * N_ + n] : 1.f;
  }
  __syncthreads();

#pragma unroll
  for (int s = 0; s < 7; s++) {
    const int kk = s * 8;
    uint32_t ax[4], ay[4];
    ax[0] = bxs[(wr + g) * 60 + kk + tg];
    ax[1] = bxs[(wr + g + 8) * 60 + kk + tg];
    ax[2] = bxs[(wr + g) * 60 + kk + tg + 4];
    ax[3] = bxs[(wr + g + 8) * 60 + kk + tg + 4];
    ay[0] = bys[(wr + g) * 60 + kk + tg];
    ay[1] = bys[(wr + g + 8) * 60 + kk + tg];
    ay[2] = bys[(wr + g) * 60 + kk + tg + 4];
    ay[3] = bys[(wr + g + 8) * 60 + kk + tg + 4];
#pragma unroll
    for (int nt = 0; nt < 4; nt++) {
      uint32_t b0 = exs[(nt * 8 + g) * 60 + kk + tg];
      uint32_t b1 = exs[(nt * 8 + g) * 60 + kk + tg + 4];
      mma16n8k8(acc[nt], ax, b0, b1);
    }
#pragma unroll
    for (int nt = 0; nt < 4; nt++) {
      uint32_t b0 = eys[(nt * 8 + g) * 60 + kk + tg];
      uint32_t b1 = eys[(nt * 8 + g) * 60 + kk + tg + 4];
      mma16n8k8(acc[4 + nt], ay, b0, b1);
    }
  }

  // ---- normalize + store ----
  const float i0 = invs[wr + g], i1 = invs[wr + g + 8];
  const int b = bh / H_, h = bh % H_;
#pragma unroll
  for (int half = 0; half < 2; half++) {
    const int n = row0 + wr + g + half * 8;
    if (n >= N_) continue;
    const float inv = half ? i1 : i0;
    float* dst = g_ao + ((size_t)b * N_ + n) * C_ + h * D_ + 2 * tg;
#pragma unroll
    for (int nt = 0; nt < 8; nt++)
      *(float2*)(dst + nt * 8) = make_float2(acc[nt][half * 2] * inv,
                                             acc[nt][half * 2 + 1] * inv);
  }
}

// ---------------- launch ----------------
extern "C" void kernel_launch(void* const* d_in, const int* in_sizes, int n_in,
                              void* d_out, int out_size) {
  const float* x = (const float*)d_in[0];
  const float* qkv_w = (const float*)d_in[1];
  const float* proj_w = (const float*)d_in[2];
  const float* qxe = (const float*)d_in[3];
  const float* qye = (const float*)d_in[4];
  const float* vxe = (const float*)d_in[5];
  const float* vye = (const float*)d_in[6];
  float* out = (float*)d_out;

  cudaFuncSetAttribute(av_mma_kernel, cudaFuncAttributeMaxDynamicSharedMemorySize,
                       AV_SMEM);

  // QKV projection (tf32 tensor cores)
  mma_gemm_kernel<0><<<dim3(18, 73), 256>>>(x, qkv_w, nullptr);

  pxpy_kernel<<<dim3(10, BH_), 256>>>(qxe, qye);

  // scores (tf32 tensor cores)
  scores_mma_kernel<<<dim3(5, 5, BH_), 256>>>();

  softmax_kernel<<<(BH_ * N_ + 7) / 8, 256>>>();

  // AV + bias (tf32 tensor cores)
  av_mma_kernel<<<dim3(5, BH_), 256, AV_SMEM>>>(vxe, vye);

  // Output projection (tf32 tensor cores)
  mma_gemm_kernel<1><<<dim3(6, 73), 256>>>(nullptr, proj_w, out);
}